// round 15
// baseline (speedup 1.0000x reference)
#include <cuda_runtime.h>
#include <stdint.h>

// -----------------------------------------------------------------------------
// Polynomial edge-energy + segment sum. (indices are int32)
// R15: node table sharded across an 8-CTA cluster's SMEM (DSMEM gathers)
//      to escape the l1tex divergent-LDG replay floor (~2.07 cyc/lane-gather).
//      Each CTA: 12500 float4 node records (195KB dyn smem), 1024 threads,
//      1 CTA/SM. Gather = magic-div rank + mapa + ld.shared::cluster.v4.
// -----------------------------------------------------------------------------

#define CLUSTER  8
#define MAX_TT   1024     // >= T*T = 625  (table sizes runtime-offset in smem)
#define MAX_G    1024     // >= n_graphs = 512

__device__ __forceinline__ uint32_t smem_u32(const void* p) {
    return (uint32_t)__cvta_generic_to_shared(p);
}

__device__ __forceinline__ float4 dsmem_gather(uint32_t shard_base, int i,
                                               unsigned magic, unsigned Npc) {
    unsigned r   = (unsigned)(((unsigned long long)(unsigned)i * magic) >> 32);
    unsigned off = (unsigned)i - r * Npc;
    uint32_t la  = shard_base + off * 16u;
    uint32_t ra;
    asm("mapa.shared::cluster.u32 %0, %1, %2;" : "=r"(ra) : "r"(la), "r"(r));
    float4 v;
    asm("ld.shared::cluster.v4.f32 {%0,%1,%2,%3}, [%4];"
        : "=f"(v.x), "=f"(v.y), "=f"(v.z), "=f"(v.w) : "r"(ra));
    return v;
}

__device__ __forceinline__ float pair_V(float4 n0, float4 n1,
                                        const float4* __restrict__ s_kk,
                                        const float* __restrict__ s_v0,
                                        int T) {
    float dx = n0.x - n1.x;
    float dy = n0.y - n1.y;
    float dz = n0.z - n1.z;
    float x2 = fmaf(dx, dx, fmaf(dy, dy, dz * dz));
    float x  = sqrtf(x2);
    int idx = __float_as_int(n0.w) * T + __float_as_int(n1.w);
    float4 k = s_kk[idx];
    float  v = s_v0[idx];
    return fmaf(x, fmaf(x, fmaf(x, fmaf(x, k.w, k.z), k.y), k.x), v);
}

// ---- main kernel (one launch does everything) ---------------------------------
__global__ void __launch_bounds__(1024, 1) __cluster_dims__(CLUSTER, 1, 1)
poly_cluster_kernel(const float* __restrict__ pos,
                    const int* __restrict__ types,
                    const int* __restrict__ map0,
                    const int* __restrict__ map1,
                    const int* __restrict__ batch,
                    const float* __restrict__ ks,
                    const float* __restrict__ v0g,
                    float* __restrict__ y,
                    int C, int E, int T, int degs, int G,
                    int N, unsigned Npc, unsigned magic) {
    extern __shared__ char smem[];
    const int TT = T * T;
    float4* sh_nodes = (float4*)smem;                       // Npc records
    float4* s_kk     = (float4*)(smem + (size_t)Npc * 16);
    float*  s_v0     = (float*)(smem + (size_t)Npc * 16 + (size_t)TT * 16);
    float*  s_y      = (float*)(smem + (size_t)Npc * 16 + (size_t)TT * 20);

    const int tid = threadIdx.x;
    unsigned rank;
    asm("mov.u32 %0, %%cluster_ctarank;" : "=r"(rank));

    // ---- fill this CTA's node shard (packed xyz + type bits) ----
    int nbase = (int)(rank * Npc);
    int ncnt  = N - nbase;
    if (ncnt > (int)Npc) ncnt = (int)Npc;
    for (int i = tid; i < ncnt; i += 1024) {
        int idx = nbase + i;
        float4 v;
        v.x = pos[3 * idx + 0];
        v.y = pos[3 * idx + 1];
        v.z = pos[3 * idx + 2];
        v.w = __int_as_float(types[idx]);
        sh_nodes[i] = v;
    }
    // ---- tables + block-local output accumulator ----
    for (int i = tid; i < TT; i += 1024) {
        float4 k;
        k.x = ks[i];
        k.y = (degs > 1) ? ks[TT + i]     : 0.f;
        k.z = (degs > 2) ? ks[2 * TT + i] : 0.f;
        k.w = (degs > 3) ? ks[3 * TT + i] : 0.f;
        s_kk[i] = k;
        s_v0[i] = v0g[i];
    }
    for (int i = tid; i < G; i += 1024) s_y[i] = 0.f;
    __syncthreads();
    // all shards in the cluster must be filled before any gather
    asm volatile("barrier.cluster.arrive.aligned;" ::: "memory");
    asm volatile("barrier.cluster.wait.aligned;" ::: "memory");

    const uint32_t shard_base = smem_u32(sh_nodes);

    const int4* __restrict__ m0v = (const int4*)map0;
    const int4* __restrict__ m1v = (const int4*)map1;
    const int4* __restrict__ bv  = (const int4*)batch;

    // contiguous per-block chunk range, uniform iteration count in block
    int cpb    = (C + (int)gridDim.x - 1) / (int)gridDim.x;
    int cstart = (int)blockIdx.x * cpb;
    int cend   = cstart + cpb;
    if (cend > C) cend = C;
    int range  = cend - cstart;
    int iters  = (range > 0) ? (range + 1023) / 1024 : 0;

    const int lane = tid & 31;

    for (int it = 0; it < iters; ++it) {
        int  c     = cstart + it * 1024 + tid;
        bool valid = (c < cend);
        float V0 = 0.f, V1 = 0.f, V2 = 0.f, V3 = 0.f;
        int4 bb = make_int4(0, 0, 0, 0);
        if (valid) {
            int4 ma = m0v[c];
            int4 mb = m1v[c];
            bb = bv[c];
            // 8 independent DSMEM gathers (smem crossbar + cluster fabric,
            // not l1tex replay)
            float4 n0 = dsmem_gather(shard_base, ma.x, magic, Npc);
            float4 n1 = dsmem_gather(shard_base, mb.x, magic, Npc);
            float4 n2 = dsmem_gather(shard_base, ma.y, magic, Npc);
            float4 n3 = dsmem_gather(shard_base, mb.y, magic, Npc);
            float4 n4 = dsmem_gather(shard_base, ma.z, magic, Npc);
            float4 n5 = dsmem_gather(shard_base, mb.z, magic, Npc);
            float4 n6 = dsmem_gather(shard_base, ma.w, magic, Npc);
            float4 n7 = dsmem_gather(shard_base, mb.w, magic, Npc);
            V0 = pair_V(n0, n1, s_kk, s_v0, T);
            V1 = pair_V(n2, n3, s_kk, s_v0, T);
            V2 = pair_V(n4, n5, s_kk, s_v0, T);
            V3 = pair_V(n6, n7, s_kk, s_v0, T);
        }
        // warp-uniform segment fast path (sorted batches); iters uniform in
        // block so every lane reaches every sync
        int bl = __shfl_sync(0xffffffffu, bb.x, 0);
        bool uni = valid && (bb.x == bl) && (bb.y == bl) &&
                            (bb.z == bl) && (bb.w == bl);
        if (__ballot_sync(0xffffffffu, uni) == 0xffffffffu) {
            float s = (V0 + V1) + (V2 + V3);
            #pragma unroll
            for (int o = 16; o > 0; o >>= 1)
                s += __shfl_xor_sync(0xffffffffu, s, o);
            if (lane == 0) atomicAdd(&s_y[bl], s);
        } else if (valid) {
            atomicAdd(&s_y[bb.x], V0);
            atomicAdd(&s_y[bb.y], V1);
            atomicAdd(&s_y[bb.z], V2);
            atomicAdd(&s_y[bb.w], V3);
        }
    }

    // trailing edges (E % 4 != 0): block 0 only (gathers still via DSMEM)
    if (blockIdx.x == 0 && tid == 0) {
        for (int e = C * 4; e < E; ++e) {
            float4 a = dsmem_gather(shard_base, map0[e], magic, Npc);
            float4 b = dsmem_gather(shard_base, map1[e], magic, Npc);
            atomicAdd(&s_y[batch[e]], pair_V(a, b, s_kk, s_v0, T));
        }
    }

    __syncthreads();
    for (int i = tid; i < G; i += 1024) {
        float v = s_y[i];
        if (v != 0.f) atomicAdd(&y[i], v);
    }
    // no CTA may exit while peers can still read its shard
    asm volatile("barrier.cluster.arrive.aligned;" ::: "memory");
    asm volatile("barrier.cluster.wait.aligned;" ::: "memory");
}

// ---- launch ------------------------------------------------------------------
extern "C" void kernel_launch(void* const* d_in, const int* in_sizes, int n_in,
                              void* d_out, int out_size) {
    const float* pos     = (const float*)d_in[0];  // (N,3)  f32
    const float* ks      = (const float*)d_in[1];  // (DEGS,T,T) f32
    const float* v0      = (const float*)d_in[2];  // (T,T) f32
    const int*   mapping = (const int*)d_in[3];    // (2,E) int32
    const int*   types   = (const int*)d_in[4];    // (N,)  int32
    const int*   mbatch  = (const int*)d_in[5];    // (E,)  int32, sorted
    float* y = (float*)d_out;                      // (G,)  f32

    const int N  = in_sizes[0] / 3;
    const int TT = in_sizes[2];           // T*T
    int T = 1;
    while ((T + 1) * (T + 1) <= TT) ++T;  // integer sqrt
    const int degs = in_sizes[1] / TT;
    const int E = in_sizes[5];
    const int G = out_size;

    const int* map0 = mapping;
    const int* map1 = mapping + E;
    const int C = E >> 2;                 // 4 edges per chunk

    const unsigned Npc   = (unsigned)((N + CLUSTER - 1) / CLUSTER);  // 12500
    const unsigned magic = (unsigned)(((1ULL << 32) + Npc - 1) / Npc);
    // exact floor(i/Npc) for i < 2^32 / (magic*Npc - 2^32)  (>> 5e5 here)

    const size_t smem_bytes = (size_t)Npc * 16 + (size_t)TT * 20
                            + (size_t)G * 4 + 64;

    cudaFuncSetAttribute(poly_cluster_kernel,
                         cudaFuncAttributeMaxDynamicSharedMemorySize,
                         (int)smem_bytes);

    cudaMemsetAsync(d_out, 0, (size_t)out_size * sizeof(float), 0);

    // 18 clusters x 8 CTAs = 144 CTAs, 1 per SM (195KB+ smem each)
    int blocks = 144;
    poly_cluster_kernel<<<blocks, 1024, smem_bytes>>>(
        pos, types, map0, map1, mbatch, ks, v0, y,
        C, E, T, degs, G, N, Npc, magic);
}

// round 16
// speedup vs baseline: 2.5998x; 2.5998x over previous
#include <cuda_runtime.h>
#include <stdint.h>

// -----------------------------------------------------------------------------
// Polynomial edge-energy + segment sum. (indices are int32)
//   per edge e: x = |pos[m0]-pos[m1]|, V = v0[t0,t1] + sum_p ks[p,t0,t1]*x^(p+1)
//   y[g] = segment sum over sorted mapping_batch
// R16: L1 SOL tracks per-thread divergent-gather batch (4->41%, 8->64%).
//      Double the burst: 8 edges/thread, 16 gathers batched before any
//      dependent compute. <=128 regs (no spills), 2 CTAs/SM, one wave.
//      Otherwise identical to the R5 champion (shuffle reduction, smem tables).
// -----------------------------------------------------------------------------

#define MAX_TT 1024        // >= T*T = 625
#define MAX_G  1024        // >= n_graphs = 512

__device__ float4 g_nodes[1 << 17];   // 131072 >= N; xyz + type-bits-as-float

// ---- prep: pack (pos, atom_type) into one float4 per node -------------------
__global__ void pack_nodes_kernel(const float* __restrict__ pos,
                                  const int* __restrict__ types,
                                  int N) {
    int i = blockIdx.x * blockDim.x + threadIdx.x;
    if (i < N) {
        float4 v;
        v.x = pos[3 * i + 0];
        v.y = pos[3 * i + 1];
        v.z = pos[3 * i + 2];
        v.w = __int_as_float(types[i]);   // bit reinterpret: free to decode
        g_nodes[i] = v;
    }
}

// ---- per-edge energy from two gathered node records --------------------------
__device__ __forceinline__ float pair_V(float4 n0, float4 n1,
                                        const float4* __restrict__ s_kk,
                                        const float* __restrict__ s_v0,
                                        int T) {
    float dx = n0.x - n1.x;
    float dy = n0.y - n1.y;
    float dz = n0.z - n1.z;
    float x2 = fmaf(dx, dx, fmaf(dy, dy, dz * dz));
    float x  = sqrtf(x2);
    int idx = __float_as_int(n0.w) * T + __float_as_int(n1.w);
    float4 k = s_kk[idx];
    float  v = s_v0[idx];
    // v0 + x*(k1 + x*(k2 + x*(k3 + x*k4)))
    return fmaf(x, fmaf(x, fmaf(x, fmaf(x, k.w, k.z), k.y), k.x), v);
}

// ---- main kernel -------------------------------------------------------------
__global__ void __launch_bounds__(256, 2)
poly_main_kernel(const int* __restrict__ map0,
                 const int* __restrict__ map1,
                 const int* __restrict__ batch,
                 const float* __restrict__ ks,
                 const float* __restrict__ v0g,
                 float* __restrict__ y,
                 int C,              // number of 4-edge chunks
                 int E,              // total edges (tail by block 0)
                 int T, int degs, int G) {
    __shared__ float4 s_kk[MAX_TT];
    __shared__ float  s_v0[MAX_TT];
    __shared__ float  s_y[MAX_G];

    const int TT = T * T;
    for (int i = threadIdx.x; i < TT; i += blockDim.x) {
        float4 k;
        k.x = ks[i];
        k.y = (degs > 1) ? ks[TT + i]     : 0.f;
        k.z = (degs > 2) ? ks[2 * TT + i] : 0.f;
        k.w = (degs > 3) ? ks[3 * TT + i] : 0.f;
        s_kk[i] = k;
        s_v0[i] = v0g[i];
    }
    for (int i = threadIdx.x; i < G; i += blockDim.x) s_y[i] = 0.f;
    __syncthreads();

    const int4* __restrict__ m0v = (const int4*)map0;
    const int4* __restrict__ m1v = (const int4*)map1;
    const int4* __restrict__ bv  = (const int4*)batch;

    // contiguous per-block chunk range, UNIFORM iteration count within block
    int cpb    = (C + (int)gridDim.x - 1) / (int)gridDim.x;
    int cstart = (int)blockIdx.x * cpb;
    int cend   = cstart + cpb;
    if (cend > C) cend = C;
    int range  = cend - cstart;
    int iters  = (range > 0) ? (range + 511) / 512 : 0;   // 512 chunks/superiter

    const int lane = threadIdx.x & 31;

    for (int it = 0; it < iters; ++it) {
        int  c1 = cstart + it * 512 + (int)threadIdx.x;
        int  c2 = c1 + 256;
        bool v1 = (c1 < cend);
        bool v2 = (c2 < cend);

        int4 ma1, mb1, bb1, ma2, mb2, bb2;
        bb1 = make_int4(0, 0, 0, 0);
        bb2 = make_int4(0, 0, 0, 0);
        if (v1) { ma1 = m0v[c1]; mb1 = m1v[c1]; bb1 = bv[c1]; }
        if (v2) { ma2 = m0v[c2]; mb2 = m1v[c2]; bb2 = bv[c2]; }

        float V0 = 0.f, V1 = 0.f, V2 = 0.f, V3 = 0.f;
        float V4 = 0.f, V5 = 0.f, V6 = 0.f, V7 = 0.f;
        if (v1) {
            // ---- 16-gather burst: all independent, issued back-to-back ----
            float4 n0  = g_nodes[ma1.x];
            float4 n1  = g_nodes[mb1.x];
            float4 n2  = g_nodes[ma1.y];
            float4 n3  = g_nodes[mb1.y];
            float4 n4  = g_nodes[ma1.z];
            float4 n5  = g_nodes[mb1.z];
            float4 n6  = g_nodes[ma1.w];
            float4 n7  = g_nodes[mb1.w];
            if (v2) {
                float4 n8  = g_nodes[ma2.x];
                float4 n9  = g_nodes[mb2.x];
                float4 n10 = g_nodes[ma2.y];
                float4 n11 = g_nodes[mb2.y];
                float4 n12 = g_nodes[ma2.z];
                float4 n13 = g_nodes[mb2.z];
                float4 n14 = g_nodes[ma2.w];
                float4 n15 = g_nodes[mb2.w];
                V4 = pair_V(n8,  n9,  s_kk, s_v0, T);
                V5 = pair_V(n10, n11, s_kk, s_v0, T);
                V6 = pair_V(n12, n13, s_kk, s_v0, T);
                V7 = pair_V(n14, n15, s_kk, s_v0, T);
            }
            V0 = pair_V(n0, n1, s_kk, s_v0, T);
            V1 = pair_V(n2, n3, s_kk, s_v0, T);
            V2 = pair_V(n4, n5, s_kk, s_v0, T);
            V3 = pair_V(n6, n7, s_kk, s_v0, T);
        }

        // warp-uniform segment fast path over BOTH chunks (sorted batches);
        // iters uniform in block so every lane reaches every sync
        int bl = __shfl_sync(0xffffffffu, bb1.x, 0);
        bool uni =
            (!v1 || (bb1.x == bl && bb1.y == bl && bb1.z == bl && bb1.w == bl)) &&
            (!v2 || (bb2.x == bl && bb2.y == bl && bb2.z == bl && bb2.w == bl));
        if (__ballot_sync(0xffffffffu, uni) == 0xffffffffu) {
            float s = ((V0 + V1) + (V2 + V3)) + ((V4 + V5) + (V6 + V7));
            #pragma unroll
            for (int o = 16; o > 0; o >>= 1)
                s += __shfl_xor_sync(0xffffffffu, s, o);
            if (lane == 0) atomicAdd(&s_y[bl], s);   // adds 0 if all-invalid
        } else {
            if (v1) {
                atomicAdd(&s_y[bb1.x], V0);
                atomicAdd(&s_y[bb1.y], V1);
                atomicAdd(&s_y[bb1.z], V2);
                atomicAdd(&s_y[bb1.w], V3);
            }
            if (v2) {
                atomicAdd(&s_y[bb2.x], V4);
                atomicAdd(&s_y[bb2.y], V5);
                atomicAdd(&s_y[bb2.z], V6);
                atomicAdd(&s_y[bb2.w], V7);
            }
        }
    }

    // trailing edges (E % 4 != 0): block 0 only
    if (blockIdx.x == 0 && threadIdx.x == 0) {
        for (int e = C * 4; e < E; ++e) {
            float4 a = g_nodes[map0[e]];
            float4 b = g_nodes[map1[e]];
            float V = pair_V(a, b, s_kk, s_v0, T);
            atomicAdd(&s_y[batch[e]], V);
        }
    }

    __syncthreads();
    // each block spans few segments -> zero-guard keeps global atomics ~2/block
    for (int i = threadIdx.x; i < G; i += blockDim.x) {
        float v = s_y[i];
        if (v != 0.f) atomicAdd(&y[i], v);
    }
}

// ---- launch ------------------------------------------------------------------
extern "C" void kernel_launch(void* const* d_in, const int* in_sizes, int n_in,
                              void* d_out, int out_size) {
    const float* pos     = (const float*)d_in[0];  // (N,3)  f32
    const float* ks      = (const float*)d_in[1];  // (DEGS,T,T) f32
    const float* v0      = (const float*)d_in[2];  // (T,T) f32
    const int*   mapping = (const int*)d_in[3];    // (2,E) int32
    const int*   types   = (const int*)d_in[4];    // (N,)  int32
    const int*   mbatch  = (const int*)d_in[5];    // (E,)  int32, sorted
    float* y = (float*)d_out;                      // (G,)  f32

    const int N  = in_sizes[0] / 3;
    const int TT = in_sizes[2];           // T*T
    int T = 1;
    while ((T + 1) * (T + 1) <= TT) ++T;  // integer sqrt
    const int degs = in_sizes[1] / TT;
    const int E = in_sizes[5];
    const int G = out_size;

    const int* map0 = mapping;
    const int* map1 = mapping + E;
    const int C = E >> 2;                 // 4 edges per chunk

    cudaMemsetAsync(d_out, 0, (size_t)out_size * sizeof(float), 0);

    int prep_blocks = (N + 255) / 256;
    pack_nodes_kernel<<<prep_blocks, 256>>>(pos, types, N);

    // one wave at 2 CTAs/SM (<=128 regs: 16 live float4 gathers, no spills)
    int blocks = 148 * 2;
    poly_main_kernel<<<blocks, 256>>>(map0, map1, mbatch, ks, v0, y,
                                      C, E, T, degs, G);
}